// round 11
// baseline (speedup 1.0000x reference)
#include <cuda_runtime.h>
#include <math.h>

#define NUM_C 512
#define DFIX  512
#define NMAX  (1 << 17)
#define NBLK  16            // blocks for count/scatter (must match both kernels)
#define GSUM  (148 * 8)     // classsum grid: one full wave, 128 thr/CTA

// ---------------- device scratch (no allocations allowed) ----------------
__device__ int   g_is64;
__device__ int   g_blkhist[NBLK * NUM_C];   // per-block class histograms
__device__ int   g_blkbase[NBLK * NUM_C];   // per-block scatter bases
__device__ int   g_counts[NUM_C];
__device__ int   g_offsets[NUM_C + 1];      // class segment starts, +sentinel n
__device__ int   g_idx[NMAX];               // row ids sorted by class
__device__ float g_cls_sums[NUM_C * DFIX];
__device__ float g_total[DFIX];
__device__ float g_term[NUM_C];

__device__ __forceinline__ int get_label(const void* p, int i, int is64) {
    if (is64) return (int)__ldg(&((const long long*)p)[i]);
    return __ldg(&((const int*)p)[i]);
}

// ---------------- kernel 1: zero cls_sums/total/term + detect label width ----------
// grid 256 x 256: each thread zeros one float4 of g_cls_sums (256*256 = 64K float4).
__global__ void k_init(const void* __restrict__ labels, int n) {
    int t = threadIdx.x, b = blockIdx.x;
    ((float4*)g_cls_sums)[b * 256 + t] = make_float4(0.f, 0.f, 0.f, 0.f);
    if (b == 0) {
        g_total[t] = 0.0f;  g_total[t + 256] = 0.0f;
        g_term[t]  = 0.0f;  g_term[t + 256]  = 0.0f;
        // int64 detection: int64 labels < 512 have all-zero odd 32-bit words.
        // int32 random labels: P(256 probed odd words all zero) = 512^-256 ~ 0.
        const int* w = (const int*)labels;
        int bad = 0;
        if (2 * t + 1 < 2 * n) bad = (w[2 * t + 1] != 0);
        int any = __syncthreads_or(bad);
        if (t == 0) g_is64 = any ? 0 : 1;
    }
}

// ---------------- kernel 2: per-block class histogram (no global atomics) --------
__global__ void k_count(const void* __restrict__ labels, int n) {
    __shared__ int h[NUM_C];
    int t = threadIdx.x, b = blockIdx.x;      // NBLK x 1024
    if (t < NUM_C) h[t] = 0;
    __syncthreads();
    int is64 = g_is64;
    for (int i = b * blockDim.x + t; i < n; i += NBLK * blockDim.x)
        atomicAdd(&h[get_label(labels, i, is64)], 1);
    __syncthreads();
    if (t < NUM_C) g_blkhist[b * NUM_C + t] = h[t];
}

// ---------------- kernel 3: class scan + per-block bases (1 block, 512 thr) ------
__global__ void k_scan() {
    __shared__ int sh[NUM_C];
    int c = threadIdx.x;
    int per[NBLK];
    int tot = 0;
    #pragma unroll
    for (int b = 0; b < NBLK; b++) { per[b] = g_blkhist[b * NUM_C + c]; tot += per[b]; }
    g_counts[c] = tot;
    sh[c] = tot;
    __syncthreads();
    for (int off = 1; off < NUM_C; off <<= 1) {
        int v = (c >= off) ? sh[c - off] : 0;
        __syncthreads();
        sh[c] += v;
        __syncthreads();
    }
    int ex = sh[c] - tot;                     // exclusive
    g_offsets[c] = ex;
    if (c == NUM_C - 1) g_offsets[NUM_C] = ex + tot;   // = n
    int run = ex;
    #pragma unroll
    for (int b = 0; b < NBLK; b++) { g_blkbase[b * NUM_C + c] = run; run += per[b]; }
}

// ---------------- kernel 4: scatter via shared-memory cursors --------------------
// Same grid/stride as k_count so block b owns exactly the rows it counted.
__global__ void k_scatter(const void* __restrict__ labels, int n) {
    __shared__ int cur[NUM_C];
    int t = threadIdx.x, b = blockIdx.x;      // NBLK x 1024
    if (t < NUM_C) cur[t] = g_blkbase[b * NUM_C + t];
    __syncthreads();
    int is64 = g_is64;
    int stride = NBLK * blockDim.x;
    int i = b * blockDim.x + t;
    for (; i + stride < n; i += 2 * stride) {  // 2x unroll: overlap label loads
        int c0 = get_label(labels, i, is64);
        int c1 = get_label(labels, i + stride, is64);
        g_idx[atomicAdd(&cur[c0], 1)] = i;
        g_idx[atomicAdd(&cur[c1], 1)] = i + stride;
    }
    if (i < n) {
        int c = get_label(labels, i, is64);
        g_idx[atomicAdd(&cur[c], 1)] = i;
    }
}

// ---------------- kernel 5: balanced streaming class-sum (the 128 MB pass) -------
// Even-chunk partition of sorted positions: CTA g sums rows [g*per,(g+1)*per),
// spanning ~1-2 classes; flushes partial float4 sums by atomicAdd. One wave.
__global__ void __launch_bounds__(128)
k_classsum(const float4* __restrict__ x, int n) {
    __shared__ int soff[NUM_C + 1];
    __shared__ int sidx[256];                   // per <= 256 supported
    int t = threadIdx.x;
    for (int k = t; k <= NUM_C; k += 128) soff[k] = g_offsets[k];

    int per = (n + gridDim.x - 1) / gridDim.x;  // 56 for n = 65536
    int s = blockIdx.x * per;
    if (s >= n) return;
    int e = min(n, s + per);
    int len = e - s;
    for (int k = t; k < len; k += 128) sidx[k] = g_idx[s + k];
    __syncthreads();

    // largest c with soff[c] <= s (uniform across threads)
    int lo = 0, hi = NUM_C;
    while (hi - lo > 1) { int mid = (lo + hi) >> 1; if (soff[mid] <= s) lo = mid; else hi = mid; }
    int c = lo;

    float4 tot = make_float4(0.f, 0.f, 0.f, 0.f);
    int pos = s;
    while (pos < e) {
        int cend = min(e, soff[c + 1]);
        if (cend > pos) {
            float4 acc = make_float4(0.f, 0.f, 0.f, 0.f);
            int j = pos - s, jend = cend - s;
            for (; j + 4 <= jend; j += 4) {
                int i0 = sidx[j], i1 = sidx[j + 1], i2 = sidx[j + 2], i3 = sidx[j + 3];
                float4 v0 = __ldcs(&x[(long long)i0 * 128 + t]);
                float4 v1 = __ldcs(&x[(long long)i1 * 128 + t]);
                float4 v2 = __ldcs(&x[(long long)i2 * 128 + t]);
                float4 v3 = __ldcs(&x[(long long)i3 * 128 + t]);
                acc.x += (v0.x + v1.x) + (v2.x + v3.x);
                acc.y += (v0.y + v1.y) + (v2.y + v3.y);
                acc.z += (v0.z + v1.z) + (v2.z + v3.z);
                acc.w += (v0.w + v1.w) + (v2.w + v3.w);
            }
            for (; j < jend; j++) {
                float4 v = __ldcs(&x[(long long)sidx[j] * 128 + t]);
                acc.x += v.x; acc.y += v.y; acc.z += v.z; acc.w += v.w;
            }
            float* dst = &g_cls_sums[c * DFIX + 4 * t];
            atomicAdd(dst + 0, acc.x);
            atomicAdd(dst + 1, acc.y);
            atomicAdd(dst + 2, acc.z);
            atomicAdd(dst + 3, acc.w);
            tot.x += acc.x; tot.y += acc.y; tot.z += acc.z; tot.w += acc.w;
        }
        pos = cend; c++;
    }
    atomicAdd(&g_total[4 * t + 0], tot.x);    // one flush per CTA
    atomicAdd(&g_total[4 * t + 1], tot.y);
    atomicAdd(&g_total[4 * t + 2], tot.z);
    atomicAdd(&g_total[4 * t + 3], tot.w);
}

// ---------------- kernel 6: per-class distance + weighted hinge term -------------
__global__ void k_loss(int n) {
    int c = blockIdx.x;
    int t = threadIdx.x;                      // 512 threads
    int cnt = __ldg(&g_counts[c]);
    if (cnt == 0) { if (t == 0) g_term[c] = 0.0f; return; }

    float s   = g_cls_sums[c * DFIX + t];
    float fc  = (float)cnt;
    float fn  = (float)n;
    float mup = s / fc;
    float mun = (g_total[t] - s) / (fn - fc);
    float xd  = mup - mun + 1e-6f;            // eps added to the difference
    float sq  = xd * xd;

    __shared__ float red[16];
    for (int o = 16; o; o >>= 1) sq += __shfl_down_sync(0xffffffffu, sq, o);
    if ((t & 31) == 0) red[t >> 5] = sq;
    __syncthreads();
    if (t < 16) {
        float v = red[t];
        for (int o = 8; o; o >>= 1) v += __shfl_down_sync(0xffffu, v, o);
        if (t == 0) {
            float dd = sqrtf(v);
            float w  = fmaxf(1.0f - dd, 0.0f); // MARGIN = 1.0
            g_term[c] = fc * w * w / fn;
        }
    }
}

// ---------------- kernel 7: deterministic fixed-order final reduce ---------------
__global__ void k_final(float* __restrict__ out) {
    __shared__ float sh[NUM_C];
    int t = threadIdx.x;                      // 512 threads
    sh[t] = g_term[t];
    __syncthreads();
    for (int o = 256; o; o >>= 1) {
        if (t < o) sh[t] += sh[t + o];
        __syncthreads();
    }
    if (t == 0) out[0] = sh[0];
}

// ---------------- launch ----------------
extern "C" void kernel_launch(void* const* d_in, const int* in_sizes, int n_in,
                              void* d_out, int out_size) {
    const float* x      = (const float*)d_in[0];
    const void*  labels = d_in[1];
    int n = in_sizes[1];
    float* out = (float*)d_out;

    k_init<<<256, 256>>>(labels, n);
    k_count<<<NBLK, 1024>>>(labels, n);
    k_scan<<<1, 512>>>();
    k_scatter<<<NBLK, 1024>>>(labels, n);
    k_classsum<<<GSUM, 128>>>((const float4*)x, n);
    k_loss<<<NUM_C, 512>>>(n);
    k_final<<<1, 512>>>(out);
}